// round 15
// baseline (speedup 1.0000x reference)
#include <cuda_runtime.h>
#include <cuda_fp16.h>
#include <cstdint>

// ---------------------------------------------------------------------------
// ConditionedConvolution2D via mma.sync fp16 single-term (fp32 accumulate)
//   X [32,128,128,32] f32 NHWC, P [32,128] f32, dense_w [128,9216] f32
//   A = P @ dense_w -> Wk[32,3,3,32,32];  out[b] = conv2d_same(X[b], Wk[b])
// x ~ fp16(x), w ~ fp16(w): per-product rel error ~2^-12 -> global ~3e-4.
// ---------------------------------------------------------------------------

#define B_       32
#define HW_      128
#define WK_PER_B 9216
#define FRAG_B   18432      // bytes of packed fp16 B-fragments per batch
#define XROW_SMEM 10400     // 130 px * 80 B (32 ci fp16 = 64B, stride 80)
#define ROWS_CTA 8
#define BUF_ROWS 10
#define NTHREADS 512
#define SMEM_TOTAL (BUF_ROWS * XROW_SMEM)   // 104000

__device__ uint4 g_wfrag4[B_ * FRAG_B / 16];

__device__ __forceinline__ uint32_t smem_u32(const void* p) {
    uint32_t a;
    asm("{ .reg .u64 t; cvta.to.shared.u64 t, %1; cvt.u32.u64 %0, t; }"
        : "=r"(a) : "l"(p));
    return a;
}
__device__ __forceinline__ void ldsm4(uint32_t* r, uint32_t addr) {
    asm volatile("ldmatrix.sync.aligned.m8n8.x4.shared.b16 {%0,%1,%2,%3}, [%4];"
        : "=r"(r[0]), "=r"(r[1]), "=r"(r[2]), "=r"(r[3]) : "r"(addr));
}
__device__ __forceinline__ void hmma(float* c, const uint32_t* a, const uint32_t* b) {
    asm volatile("mma.sync.aligned.m16n8k16.row.col.f32.f16.f16.f32 "
        "{%0,%1,%2,%3}, {%4,%5,%6,%7}, {%8,%9}, {%0,%1,%2,%3};"
        : "+f"(c[0]), "+f"(c[1]), "+f"(c[2]), "+f"(c[3])
        : "r"(a[0]), "r"(a[1]), "r"(a[2]), "r"(a[3]), "r"(b[0]), "r"(b[1]));
}
__device__ __forceinline__ uint32_t pkh(float a, float b) {
    __half2 h = __floats2half2_rn(a, b);
    return *reinterpret_cast<uint32_t*>(&h);
}

// ---------------------------------------------------------------------------
// Kernel 1: hypernetwork GEMM; writes fp16 weights directly in mma-B fragment
// layout:  g_wfrag[b][tap][n][lane][4 x u32]
// grid (36, 8), 256 threads; each block handles 4 batches.
// ---------------------------------------------------------------------------
__global__ __launch_bounds__(256)
void wgemm_kernel(const float* __restrict__ P, const float* __restrict__ Dw) {
    __shared__ float sp[512];
    const int b0 = blockIdx.y * 4;
    const int j  = blockIdx.x * 256 + threadIdx.x;    // 0..9215

    for (int i = threadIdx.x; i < 512; i += 256) sp[i] = P[b0 * 128 + i];
    __syncthreads();

    float acc[4];
#pragma unroll
    for (int bb = 0; bb < 4; ++bb) acc[bb] = 0.f;

    const float* dcol = Dw + j;
#pragma unroll
    for (int k0 = 0; k0 < 128; k0 += 32) {
        float dv[32];
#pragma unroll
        for (int u = 0; u < 32; ++u)
            dv[u] = dcol[(size_t)(k0 + u) * WK_PER_B];
#pragma unroll
        for (int u = 0; u < 32; ++u)
#pragma unroll
            for (int bb = 0; bb < 4; ++bb)
                acc[bb] = fmaf(sp[bb * 128 + k0 + u], dv[u], acc[bb]);
    }

    // j = ((ky*3+kx)*32 + ci)*32 + co
    const int tap = j >> 10, ci = (j >> 5) & 31, co = j & 31;
    const int h = ci >> 4, p = (ci >> 3) & 1;
    const int lane = ((co & 7) << 2) | ((ci >> 1) & 3);
    const int n = co >> 3, q = h * 2 + p;
    const int off = (((tap * 4 + n) * 32 + lane) * 4 + q) * 4 + (ci & 1) * 2;

#pragma unroll
    for (int bb = 0; bb < 4; ++bb) {
        const __half hv = __float2half_rn(acc[bb]);
        unsigned char* base =
            reinterpret_cast<unsigned char*>(g_wfrag4) + (size_t)(b0 + bb) * FRAG_B;
        *(unsigned short*)(base + off) = *(const unsigned short*)&hv;
    }
}

// ---------------------------------------------------------------------------
// Kernel 2: HMMA conv. grid (16, 32): (8-row block, batch). 512 threads.
// Warp w (16): output row r = w>>1 (0..7), px half px0 = (w&1)*64.
// One staging phase per 8 output rows (amp 1.25x); mainloop identical to the
// best-measured R10 tap loop (B reused over 4 t-tiles, A double-buffered).
// ---------------------------------------------------------------------------
__global__ __launch_bounds__(NTHREADS, 1)
void conv_hmma(const float* __restrict__ X, float* __restrict__ Out) {
    extern __shared__ __align__(128) unsigned char smem[];
    const int tid = threadIdx.x, wid = tid >> 5, lid = tid & 31;
    const int b = blockIdx.y;
    const int y0 = blockIdx.x * ROWS_CTA;

    // ---- stage X rows y0-1..y0+8 as [row][sp 0..129][32 ci fp16] ----
    {
        const float4* Xb = (const float4*)(X + (size_t)b * HW_ * HW_ * 32);
        for (int i = tid; i < BUF_ROWS * 130 * 8; i += NTHREADS) {
            const int cic = i & 7, sp = (i >> 3) % 130, ir = i / (130 * 8);
            const int gy = y0 - 1 + ir, gx = sp - 1;
            float4 v = make_float4(0.f, 0.f, 0.f, 0.f);
            if ((unsigned)gy < (unsigned)HW_ && (unsigned)gx < (unsigned)HW_)
                v = Xb[(gy * HW_ + gx) * 8 + cic];
            uint2 hh;
            hh.x = pkh(v.x, v.y);
            hh.y = pkh(v.z, v.w);
            *(uint2*)(smem + ir * XROW_SMEM + sp * 80 + cic * 8) = hh;
        }
    }
    __syncthreads();

    const int r = wid >> 1, px0 = (wid & 1) * 64;
    // ldmatrix per-lane row/col selectors
    const int arow  = (lid & 7) + ((lid >> 3) & 1) * 8;  // pixel within 16
    const int acol8 = ((lid >> 4) & 1) * 8;              // k col within 16

    const uint32_t xbase = smem_u32(smem);
    const uint4* wsrc = g_wfrag4 + (size_t)b * (FRAG_B / 16) + lid;

    float acc[4][4][4];
#pragma unroll
    for (int t = 0; t < 4; ++t)
#pragma unroll
        for (int n = 0; n < 4; ++n)
#pragma unroll
            for (int c = 0; c < 4; ++c) acc[t][n][c] = 0.f;

#pragma unroll
    for (int tap = 0; tap < 9; ++tap) {
        const int ky = tap / 3, kx = tap % 3;

        // ---- B fragments: 4 independent LDG.128, reused over 4 t-tiles ----
        uint4 Bf[4];
#pragma unroll
        for (int n = 0; n < 4; ++n)
            Bf[n] = wsrc[(tap * 4 + n) * 32];

        const uint32_t xrow = xbase + (uint32_t)((r + ky) * XROW_SMEM);
        const uint32_t abase = xrow + (uint32_t)((px0 + kx + arow) * 80 + acol8 * 2);

        // ---- A double-buffered across t: load t+1 while computing t ----
        uint32_t A[2][2][4];   // [buf][s]
#pragma unroll
        for (int s = 0; s < 2; ++s)
            ldsm4(A[0][s], abase + (uint32_t)(s * 32));

#pragma unroll
        for (int t = 0; t < 4; ++t) {
            const int cur = t & 1, nxt = cur ^ 1;
            if (t < 3) {
#pragma unroll
                for (int s = 0; s < 2; ++s)
                    ldsm4(A[nxt][s], abase + (uint32_t)((t + 1) * 16 * 80 + s * 32));
            }
#pragma unroll
            for (int n = 0; n < 4; ++n) {
                hmma(acc[t][n], A[cur][0], &Bf[n].x);   // k-tile 0 (ci 0-15)
                hmma(acc[t][n], A[cur][1], &Bf[n].z);   // k-tile 1 (ci 16-31)
            }
        }
    }

    // ---- store C fragments: out[b][y0+r][px][co] ----
    float* outb = Out + ((size_t)b * HW_ + (size_t)(y0 + r)) * HW_ * 32;
#pragma unroll
    for (int t = 0; t < 4; ++t) {
#pragma unroll
        for (int n = 0; n < 4; ++n) {
            const int px = px0 + t * 16 + (lid >> 2);
            const int co = n * 8 + (lid & 3) * 2;
            *(float2*)(outb + px * 32 + co) =
                make_float2(acc[t][n][0], acc[t][n][1]);
            *(float2*)(outb + (px + 8) * 32 + co) =
                make_float2(acc[t][n][2], acc[t][n][3]);
        }
    }
}

// ---------------------------------------------------------------------------
extern "C" void kernel_launch(void* const* d_in, const int* in_sizes, int n_in,
                              void* d_out, int out_size) {
    const float* X  = (const float*)d_in[0];
    const float* P  = (const float*)d_in[1];
    const float* Dw = (const float*)d_in[2];
    float* Out = (float*)d_out;

    wgemm_kernel<<<dim3(36, 8), 256>>>(P, Dw);

    cudaFuncSetAttribute(conv_hmma, cudaFuncAttributeMaxDynamicSharedMemorySize,
                         SMEM_TOTAL);
    conv_hmma<<<dim3(HW_ / ROWS_CTA, B_), NTHREADS, SMEM_TOTAL>>>(X, Out);
}

// round 16
// speedup vs baseline: 1.0518x; 1.0518x over previous
#include <cuda_runtime.h>
#include <cuda_fp16.h>
#include <cstdint>

// ---------------------------------------------------------------------------
// ConditionedConvolution2D via mma.sync fp16 single-term (fp32 accumulate)
//   X [32,128,128,32] f32 NHWC, P [32,128] f32, dense_w [128,9216] f32
//   A = P @ dense_w -> Wk[32,3,3,32,32];  out[b] = conv2d_same(X[b], Wk[b])
// x ~ fp16(x), w ~ fp16(w): per-product rel error ~2^-12 -> global ~3e-4.
// ---------------------------------------------------------------------------

#define B_       32
#define HW_      128
#define WK_PER_B 9216
#define FRAG_B   18432      // bytes of packed fp16 B-fragments per batch
#define XROW_SMEM 10400     // 130 px * 80 B (32 ci fp16 = 64B, stride 80)
#define ROWS_CTA 4
#define BUF_ROWS 6
#define SMEM_TOTAL (BUF_ROWS * XROW_SMEM)   // 62400

__device__ uint4 g_wfrag4[B_ * FRAG_B / 16];

__device__ __forceinline__ uint32_t smem_u32(const void* p) {
    uint32_t a;
    asm("{ .reg .u64 t; cvta.to.shared.u64 t, %1; cvt.u32.u64 %0, t; }"
        : "=r"(a) : "l"(p));
    return a;
}
__device__ __forceinline__ void ldsm4(uint32_t* r, uint32_t addr) {
    asm volatile("ldmatrix.sync.aligned.m8n8.x4.shared.b16 {%0,%1,%2,%3}, [%4];"
        : "=r"(r[0]), "=r"(r[1]), "=r"(r[2]), "=r"(r[3]) : "r"(addr));
}
__device__ __forceinline__ void hmma(float* c, const uint32_t* a, const uint32_t* b) {
    asm volatile("mma.sync.aligned.m16n8k16.row.col.f32.f16.f16.f32 "
        "{%0,%1,%2,%3}, {%4,%5,%6,%7}, {%8,%9}, {%0,%1,%2,%3};"
        : "+f"(c[0]), "+f"(c[1]), "+f"(c[2]), "+f"(c[3])
        : "r"(a[0]), "r"(a[1]), "r"(a[2]), "r"(a[3]), "r"(b[0]), "r"(b[1]));
}
__device__ __forceinline__ uint32_t pkh(float a, float b) {
    __half2 h = __floats2half2_rn(a, b);
    return *reinterpret_cast<uint32_t*>(&h);
}

// ---------------------------------------------------------------------------
// Kernel 1: hypernetwork GEMM, read-once j-tiled.
// grid (288), 256 threads. CTA owns j-slice [j0, j0+32); stages Dw slice
// (16KB, read ONCE chip-wide) + full P (16KB, L2-hit) in smem.
// Thread = (j-group of 4, batch): 512 FMA + 256 LDS. Writes fp16 fragments.
// ---------------------------------------------------------------------------
__global__ __launch_bounds__(256)
void wgemm_kernel(const float* __restrict__ P, const float* __restrict__ Dw) {
    __shared__ float sp[B_ * 128];       // 16KB: all of P
    __shared__ float sdw[128 * 32];      // 16KB: Dw[k=0..127][j-slice of 32]
    const int tid = threadIdx.x;
    const int j0 = blockIdx.x * 32;

    // stage P (4096 floats)
    for (int i = tid; i < B_ * 128; i += 256) sp[i] = P[i];
    // stage Dw slice: sdw[k*32 + jj] ; 1024 float4 loads
    {
        float4* s4 = reinterpret_cast<float4*>(sdw);
#pragma unroll
        for (int i = tid; i < 1024; i += 256) {
            const int k = i >> 3, c = i & 7;
            s4[i] = *reinterpret_cast<const float4*>(
                Dw + (size_t)k * WK_PER_B + j0 + c * 4);
        }
    }
    __syncthreads();

    const int jg = tid & 7;       // j-group: 4 consecutive j
    const int b  = tid >> 3;      // batch 0..31
    const float4* sdw4 = reinterpret_cast<const float4*>(sdw) + jg;
    const float* spb = sp + b * 128;

    float acc[4] = {0.f, 0.f, 0.f, 0.f};
#pragma unroll
    for (int k0 = 0; k0 < 128; k0 += 8) {
#pragma unroll
        for (int u = 0; u < 8; ++u) {
            const float4 dw = sdw4[(k0 + u) * 8];
            const float pv = spb[k0 + u];
            acc[0] = fmaf(pv, dw.x, acc[0]);
            acc[1] = fmaf(pv, dw.y, acc[1]);
            acc[2] = fmaf(pv, dw.z, acc[2]);
            acc[3] = fmaf(pv, dw.w, acc[3]);
        }
    }

    // write 4 fp16 values in mma-B fragment layout
    unsigned char* base =
        reinterpret_cast<unsigned char*>(g_wfrag4) + (size_t)b * FRAG_B;
#pragma unroll
    for (int c = 0; c < 4; ++c) {
        const int j = j0 + jg * 4 + c;   // ((ky*3+kx)*32 + ci)*32 + co
        const int tap = j >> 10, ci = (j >> 5) & 31, co = j & 31;
        const int h = ci >> 4, p = (ci >> 3) & 1;
        const int lane = ((co & 7) << 2) | ((ci >> 1) & 3);
        const int n = co >> 3, q = h * 2 + p;
        const int off = (((tap * 4 + n) * 32 + lane) * 4 + q) * 4 + (ci & 1) * 2;
        const __half hv = __float2half_rn(acc[c]);
        *(unsigned short*)(base + off) = *(const unsigned short*)&hv;
    }
}

// ---------------------------------------------------------------------------
// Kernel 2: HMMA conv (exact R10/R14 best config, conv=44.2us).
// grid (32, 32): (4-row block, batch). 256 threads.
// Warp w (8): output row r = w>>1, px half px0 = (w&1)*64 (4 m16 tiles).
// Per tap: 4 B-LDG.128 reused over 4 t-tiles; A double-buffered per t.
// ---------------------------------------------------------------------------
__global__ __launch_bounds__(256, 2)
void conv_hmma(const float* __restrict__ X, float* __restrict__ Out) {
    extern __shared__ __align__(128) unsigned char smem[];
    const int tid = threadIdx.x, wid = tid >> 5, lid = tid & 31;
    const int b = blockIdx.y;
    const int y0 = blockIdx.x * ROWS_CTA;

    // ---- stage X rows y0-1..y0+4 as [row][sp 0..129][32 ci fp16] ----
    {
        const float4* Xb = (const float4*)(X + (size_t)b * HW_ * HW_ * 32);
        for (int i = tid; i < BUF_ROWS * 130 * 8; i += 256) {
            const int cic = i & 7, sp = (i >> 3) % 130, ir = i / (130 * 8);
            const int gy = y0 - 1 + ir, gx = sp - 1;
            float4 v = make_float4(0.f, 0.f, 0.f, 0.f);
            if ((unsigned)gy < (unsigned)HW_ && (unsigned)gx < (unsigned)HW_)
                v = Xb[(gy * HW_ + gx) * 8 + cic];
            uint2 hh;
            hh.x = pkh(v.x, v.y);
            hh.y = pkh(v.z, v.w);
            *(uint2*)(smem + ir * XROW_SMEM + sp * 80 + cic * 8) = hh;
        }
    }
    __syncthreads();

    const int r = wid >> 1, px0 = (wid & 1) * 64;
    // ldmatrix per-lane row/col selectors
    const int arow  = (lid & 7) + ((lid >> 3) & 1) * 8;  // pixel within 16
    const int acol8 = ((lid >> 4) & 1) * 8;              // k col within 16

    const uint32_t xbase = smem_u32(smem);
    const uint4* wsrc = g_wfrag4 + (size_t)b * (FRAG_B / 16) + lid;

    float acc[4][4][4];
#pragma unroll
    for (int t = 0; t < 4; ++t)
#pragma unroll
        for (int n = 0; n < 4; ++n)
#pragma unroll
            for (int c = 0; c < 4; ++c) acc[t][n][c] = 0.f;

#pragma unroll
    for (int tap = 0; tap < 9; ++tap) {
        const int ky = tap / 3, kx = tap % 3;

        // ---- B fragments: 4 independent LDG.128, reused over 4 t-tiles ----
        uint4 Bf[4];
#pragma unroll
        for (int n = 0; n < 4; ++n)
            Bf[n] = wsrc[(tap * 4 + n) * 32];

        const uint32_t xrow = xbase + (uint32_t)((r + ky) * XROW_SMEM);
        const uint32_t abase = xrow + (uint32_t)((px0 + kx + arow) * 80 + acol8 * 2);

        // ---- A double-buffered across t: load t+1 while computing t ----
        uint32_t A[2][2][4];   // [buf][s]
#pragma unroll
        for (int s = 0; s < 2; ++s)
            ldsm4(A[0][s], abase + (uint32_t)(s * 32));

#pragma unroll
        for (int t = 0; t < 4; ++t) {
            const int cur = t & 1, nxt = cur ^ 1;
            if (t < 3) {
#pragma unroll
                for (int s = 0; s < 2; ++s)
                    ldsm4(A[nxt][s], abase + (uint32_t)((t + 1) * 16 * 80 + s * 32));
            }
#pragma unroll
            for (int n = 0; n < 4; ++n) {
                hmma(acc[t][n], A[cur][0], &Bf[n].x);   // k-tile 0 (ci 0-15)
                hmma(acc[t][n], A[cur][1], &Bf[n].z);   // k-tile 1 (ci 16-31)
            }
        }
    }

    // ---- store C fragments: out[b][y0+r][px][co] ----
    float* outb = Out + ((size_t)b * HW_ + (size_t)(y0 + r)) * HW_ * 32;
#pragma unroll
    for (int t = 0; t < 4; ++t) {
#pragma unroll
        for (int n = 0; n < 4; ++n) {
            const int px = px0 + t * 16 + (lid >> 2);
            const int co = n * 8 + (lid & 3) * 2;
            *(float2*)(outb + px * 32 + co) =
                make_float2(acc[t][n][0], acc[t][n][1]);
            *(float2*)(outb + (px + 8) * 32 + co) =
                make_float2(acc[t][n][2], acc[t][n][3]);
        }
    }
}

// ---------------------------------------------------------------------------
extern "C" void kernel_launch(void* const* d_in, const int* in_sizes, int n_in,
                              void* d_out, int out_size) {
    const float* X  = (const float*)d_in[0];
    const float* P  = (const float*)d_in[1];
    const float* Dw = (const float*)d_in[2];
    float* Out = (float*)d_out;

    wgemm_kernel<<<dim3(288), 256>>>(P, Dw);

    cudaFuncSetAttribute(conv_hmma, cudaFuncAttributeMaxDynamicSharedMemorySize,
                         SMEM_TOTAL);
    conv_hmma<<<dim3(HW_ / ROWS_CTA, B_), 256, SMEM_TOTAL>>>(X, Out);
}

// round 17
// speedup vs baseline: 1.1614x; 1.1042x over previous
#include <cuda_runtime.h>
#include <cuda_fp16.h>
#include <cstdint>

// ---------------------------------------------------------------------------
// ConditionedConvolution2D, fused single-grid: wgemm CTAs + conv CTAs with an
// in-kernel dependency (conv stages X while wgemm runs, then spin-waits).
//   X [32,128,128,32] f32 NHWC, P [32,128] f32, dense_w [128,9216] f32
// x ~ fp16(x), w ~ fp16(w): per-product rel error ~2^-12 -> global ~3e-4.
// ---------------------------------------------------------------------------

#define B_       32
#define HW_      128
#define WK_PER_B 9216
#define FRAG_B   18432      // bytes of packed fp16 B-fragments per batch
#define XROW_SMEM 10400     // 130 px * 80 B (32 ci fp16 = 64B, stride 80)
#define ROWS_CTA 4
#define BUF_ROWS 6
#define SMEM_TOTAL (BUF_ROWS * XROW_SMEM)   // 62400
#define N_WG 288            // wgemm CTAs (bids 0..287)

__device__ uint4 g_wfrag4[B_ * FRAG_B / 16];
__device__ unsigned g_done;

__device__ __forceinline__ uint32_t smem_u32(const void* p) {
    uint32_t a;
    asm("{ .reg .u64 t; cvta.to.shared.u64 t, %1; cvt.u32.u64 %0, t; }"
        : "=r"(a) : "l"(p));
    return a;
}
__device__ __forceinline__ void ldsm4(uint32_t* r, uint32_t addr) {
    asm volatile("ldmatrix.sync.aligned.m8n8.x4.shared.b16 {%0,%1,%2,%3}, [%4];"
        : "=r"(r[0]), "=r"(r[1]), "=r"(r[2]), "=r"(r[3]) : "r"(addr));
}
__device__ __forceinline__ void hmma(float* c, const uint32_t* a, const uint32_t* b) {
    asm volatile("mma.sync.aligned.m16n8k16.row.col.f32.f16.f16.f32 "
        "{%0,%1,%2,%3}, {%4,%5,%6,%7}, {%8,%9}, {%0,%1,%2,%3};"
        : "+f"(c[0]), "+f"(c[1]), "+f"(c[2]), "+f"(c[3])
        : "r"(a[0]), "r"(a[1]), "r"(a[2]), "r"(a[3]), "r"(b[0]), "r"(b[1]));
}
__device__ __forceinline__ uint32_t pkh(float a, float b) {
    __half2 h = __floats2half2_rn(a, b);
    return *reinterpret_cast<uint32_t*>(&h);
}

// ---------------------------------------------------------------------------
// Fused kernel. grid = N_WG + 1024, block 256, dyn smem 62400.
//   bid <  N_WG : hypernetwork GEMM (R14 version; b-group = bid/36, j-blk = bid%36)
//   bid >= N_WG : conv CTA (b = cid>>5, y-block = cid&31); stages X first,
//                 then waits for g_done == N_WG, then R14 mainloop.
// ---------------------------------------------------------------------------
__global__ __launch_bounds__(256, 2)
void fused_kernel(const float* __restrict__ X, const float* __restrict__ P,
                  const float* __restrict__ Dw, float* __restrict__ Out) {
    extern __shared__ __align__(128) unsigned char smem[];
    const int tid = threadIdx.x;
    const int bid = blockIdx.x;

    if (bid < N_WG) {
        // ================= wgemm portion (exact R14 algorithm) =============
        float* sp = reinterpret_cast<float*>(smem);   // 512 floats
        const int b0 = (bid / 36) * 4;
        const int j  = (bid % 36) * 256 + tid;        // 0..9215

        for (int i = tid; i < 512; i += 256) sp[i] = P[b0 * 128 + i];
        __syncthreads();

        float acc[4];
#pragma unroll
        for (int bb = 0; bb < 4; ++bb) acc[bb] = 0.f;

        const float* dcol = Dw + j;
#pragma unroll
        for (int k0 = 0; k0 < 128; k0 += 32) {
            float dv[32];
#pragma unroll
            for (int u = 0; u < 32; ++u)
                dv[u] = dcol[(size_t)(k0 + u) * WK_PER_B];
#pragma unroll
            for (int u = 0; u < 32; ++u)
#pragma unroll
                for (int bb = 0; bb < 4; ++bb)
                    acc[bb] = fmaf(sp[bb * 128 + k0 + u], dv[u], acc[bb]);
        }

        // j = ((ky*3+kx)*32 + ci)*32 + co
        const int tap = j >> 10, ci = (j >> 5) & 31, co = j & 31;
        const int h = ci >> 4, p = (ci >> 3) & 1;
        const int lane = ((co & 7) << 2) | ((ci >> 1) & 3);
        const int n = co >> 3, q = h * 2 + p;
        const int off = (((tap * 4 + n) * 32 + lane) * 4 + q) * 4 + (ci & 1) * 2;

#pragma unroll
        for (int bb = 0; bb < 4; ++bb) {
            const __half hv = __float2half_rn(acc[bb]);
            unsigned char* base =
                reinterpret_cast<unsigned char*>(g_wfrag4) + (size_t)(b0 + bb) * FRAG_B;
            *(unsigned short*)(base + off) = *(const unsigned short*)&hv;
        }

        __threadfence();        // publish g_wfrag4 stores
        __syncthreads();        // all threads' stores done before arrive
        if (tid == 0) atomicAdd(&g_done, 1u);
        return;
    }

    // ==================== conv portion (exact R14 algorithm) ===============
    const int cid = bid - N_WG;
    const int b = cid >> 5;
    const int y0 = (cid & 31) * ROWS_CTA;
    const int wid = tid >> 5, lid = tid & 31;

    // ---- stage X rows y0-1..y0+4 (independent of wgemm -> overlaps it) ----
    {
        const float4* Xb = (const float4*)(X + (size_t)b * HW_ * HW_ * 32);
        for (int i = tid; i < BUF_ROWS * 130 * 8; i += 256) {
            const int cic = i & 7, sp = (i >> 3) % 130, ir = i / (130 * 8);
            const int gy = y0 - 1 + ir, gx = sp - 1;
            float4 v = make_float4(0.f, 0.f, 0.f, 0.f);
            if ((unsigned)gy < (unsigned)HW_ && (unsigned)gx < (unsigned)HW_)
                v = Xb[(gy * HW_ + gx) * 8 + cic];
            uint2 hh;
            hh.x = pkh(v.x, v.y);
            hh.y = pkh(v.z, v.w);
            *(uint2*)(smem + ir * XROW_SMEM + sp * 80 + cic * 8) = hh;
        }
    }
    __syncthreads();

    // ---- wait for all wgemm CTAs ----
    if (tid == 0) {
        while (atomicAdd(&g_done, 0u) < (unsigned)N_WG) __nanosleep(64);
        __threadfence();
    }
    __syncthreads();

    const int r = wid >> 1, px0 = (wid & 1) * 64;
    const int arow  = (lid & 7) + ((lid >> 3) & 1) * 8;  // pixel within 16
    const int acol8 = ((lid >> 4) & 1) * 8;              // k col within 16

    const uint32_t xbase = smem_u32(smem);
    const uint4* wsrc = g_wfrag4 + (size_t)b * (FRAG_B / 16) + lid;

    float acc[4][4][4];
#pragma unroll
    for (int t = 0; t < 4; ++t)
#pragma unroll
        for (int n = 0; n < 4; ++n)
#pragma unroll
            for (int c = 0; c < 4; ++c) acc[t][n][c] = 0.f;

#pragma unroll
    for (int tap = 0; tap < 9; ++tap) {
        const int ky = tap / 3, kx = tap % 3;

        // ---- B fragments: 4 independent LDG.128, reused over 4 t-tiles ----
        uint4 Bf[4];
#pragma unroll
        for (int n = 0; n < 4; ++n)
            Bf[n] = wsrc[(tap * 4 + n) * 32];

        const uint32_t xrow = xbase + (uint32_t)((r + ky) * XROW_SMEM);
        const uint32_t abase = xrow + (uint32_t)((px0 + kx + arow) * 80 + acol8 * 2);

        // ---- A double-buffered across t: load t+1 while computing t ----
        uint32_t A[2][2][4];   // [buf][s]
#pragma unroll
        for (int s = 0; s < 2; ++s)
            ldsm4(A[0][s], abase + (uint32_t)(s * 32));

#pragma unroll
        for (int t = 0; t < 4; ++t) {
            const int cur = t & 1, nxt = cur ^ 1;
            if (t < 3) {
#pragma unroll
                for (int s = 0; s < 2; ++s)
                    ldsm4(A[nxt][s], abase + (uint32_t)((t + 1) * 16 * 80 + s * 32));
            }
#pragma unroll
            for (int n = 0; n < 4; ++n) {
                hmma(acc[t][n], A[cur][0], &Bf[n].x);   // k-tile 0 (ci 0-15)
                hmma(acc[t][n], A[cur][1], &Bf[n].z);   // k-tile 1 (ci 16-31)
            }
        }
    }

    // ---- store C fragments: out[b][y0+r][px][co] ----
    float* outb = Out + ((size_t)b * HW_ + (size_t)(y0 + r)) * HW_ * 32;
#pragma unroll
    for (int t = 0; t < 4; ++t) {
#pragma unroll
        for (int n = 0; n < 4; ++n) {
            const int px = px0 + t * 16 + (lid >> 2);
            const int co = n * 8 + (lid & 3) * 2;
            *(float2*)(outb + px * 32 + co) =
                make_float2(acc[t][n][0], acc[t][n][1]);
            *(float2*)(outb + (px + 8) * 32 + co) =
                make_float2(acc[t][n][2], acc[t][n][3]);
        }
    }
}

// ---------------------------------------------------------------------------
extern "C" void kernel_launch(void* const* d_in, const int* in_sizes, int n_in,
                              void* d_out, int out_size) {
    const float* X  = (const float*)d_in[0];
    const float* P  = (const float*)d_in[1];
    const float* Dw = (const float*)d_in[2];
    float* Out = (float*)d_out;

    // reset the cross-CTA dependency counter (graph-capturable memset node)
    void* done_ptr = nullptr;
    cudaGetSymbolAddress(&done_ptr, g_done);
    cudaMemsetAsync(done_ptr, 0, sizeof(unsigned));

    cudaFuncSetAttribute(fused_kernel, cudaFuncAttributeMaxDynamicSharedMemorySize,
                         SMEM_TOTAL);
    fused_kernel<<<dim3(N_WG + 1024), 256, SMEM_TOTAL>>>(X, P, Dw, Out);
}